// round 14
// baseline (speedup 1.0000x reference)
#include <cuda_runtime.h>

#define B_ 8
#define P_ 32
#define S_ 512
#define D_ 64

// Device scratch (allocation-free rule: __device__ globals)
__device__ __align__(16) float g_tpe[(size_t)B_ * S_ * 16];
__device__ __align__(16) float g_E[(size_t)B_ * S_ * S_];   // 8 MB, L2-resident

// ---------------- packed f32x2 helpers (u64 carriers for "l" constraint) ----------------
typedef unsigned long long u64;
__device__ __forceinline__ u64 pack2(float v) {
    u64 d; asm("mov.b64 %0, {%1, %1};" : "=l"(d) : "f"(v)); return d;
}
__device__ __forceinline__ void ffma2(u64& a, u64 x, u64 w) {
    asm("fma.rn.f32x2 %0, %1, %2, %0;" : "+l"(a) : "l"(x), "l"(w));
}
__device__ __forceinline__ void unpack2(u64 d, float& lo, float& hi) {
    asm("mov.b64 {%0, %1}, %2;" : "=f"(lo), "=f"(hi) : "l"(d));
}

// ---------------- Kernel A: normalize t + sinusoidal TPE ----------------
__global__ void k_tpe(const float* __restrict__ t, const float* __restrict__ alpha_w) {
    __shared__ float sred[S_];
    int b = blockIdx.x, tid = threadIdx.x;
    float tv = t[(size_t)b * S_ + tid];

    sred[tid] = tv; __syncthreads();
    for (int s = S_ / 2; s > 0; s >>= 1) {
        if (tid < s) sred[tid] = fminf(sred[tid], sred[tid + s]);
        __syncthreads();
    }
    float tmin = sred[0]; __syncthreads();
    sred[tid] = tv; __syncthreads();
    for (int s = S_ / 2; s > 0; s >>= 1) {
        if (tid < s) sred[tid] = fmaxf(sred[tid], sred[tid + s]);
        __syncthreads();
    }
    float tmax = sred[0];

    float z = alpha_w[0] * 1000.0f;
    float scale = (z > 0.0f) ? (z + 1.0f) : expf(z);   // elu(z)+1
    float tn = scale * (tv - tmin) / (tmax - tmin);

    const float lbase = -1.1512925464970229f;  // -ln(10000)/8
    float* dst = g_tpe + ((size_t)b * S_ + tid) * 16;
#pragma unroll
    for (int k = 0; k < 8; k++) {
        float dk = expf(lbase * (float)k);
        float sv, cv;
        sincosf(tn * dk, &sv, &cv);
        dst[2 * k] = sv;
        dst[2 * k + 1] = cv;
    }
}

// ---------------- Kernel B: E[b,s,t] = exp(dot16(tpe_s, tpe_t) / 4) ----------------
__global__ void k_escore() {
    __shared__ float tp[S_ * 17];   // pad 16->17 to kill bank conflicts
    int b = blockIdx.x >> 5;
    int chunk = blockIdx.x & 31;
    int tid = threadIdx.x;          // 256 threads

    for (int i = tid; i < S_ * 16; i += 256) {
        int r = i >> 4, c = i & 15;
        tp[r * 17 + c] = g_tpe[(size_t)b * S_ * 16 + i];
    }
    __syncthreads();

    int s0 = chunk * 16;
    float* Eb = g_E + (size_t)b * S_ * S_;
#pragma unroll 1
    for (int k = 0; k < 32; k++) {
        int idx = k * 256 + tid;         // 16 rows x 512 cols
        int sr = idx >> 9, tt = idx & 511;
        const float* q = tp + (size_t)(s0 + sr) * 17;
        const float* kv = tp + (size_t)tt * 17;
        float d = 0.0f;
#pragma unroll
        for (int c = 0; c < 16; c++) d += q[c] * kv[c];
        Eb[(size_t)(s0 + sr) * S_ + tt] = __expf(d * 0.25f);
    }
}

// ---------------- Kernel C: masked attention per (b,p) ----------------
// smem layout (floats): m_row[512] | kidx[512] | qidx[512] | meta[64] | Xs[512*64] | Ews[16*1024]
__global__ void __launch_bounds__(512, 1) k_attn(const float* __restrict__ x,
                                                 const float* __restrict__ mask,
                                                 float* __restrict__ out) {
    extern __shared__ float sm[];
    float* m_row = sm;                       // 512
    int* kidx = (int*)(sm + 512);            // 512
    int* qidx = kidx + 512;                  // 512
    int* meta = qidx + 512;                  // 64
    float* Xs = (float*)(meta + 64);         // 512*64 (pair layout)
    float* Ews = Xs + 512 * 64;              // 16 warps * 2 rows * 512

    const int tid = threadIdx.x;
    const int lane = tid & 31;
    const int wid = tid >> 5;
    const int bp = blockIdx.x;               // b*32 + p
    const int b = bp >> 5;

    // ---- phase 0: mask + ballot compaction ----
    float m = mask[(size_t)bp * S_ + tid];
    m_row[tid] = m;
    bool isKey = (m >= 0.5f);
    unsigned bal = __ballot_sync(0xffffffffu, isKey);
    if (lane == 0) meta[wid] = __popc(bal);
    __syncthreads();
    if (tid == 0) {
        int aK = 0, aQ = 0;
#pragma unroll
        for (int w = 0; w < 16; w++) {
            int ck = meta[w];
            meta[16 + w] = aK;   // key offset per warp
            meta[32 + w] = aQ;   // query offset per warp
            aK += ck; aQ += 32 - ck;
        }
        meta[48] = aK;  // nk
        meta[49] = aQ;  // nq
    }
    __syncthreads();
    int rank = __popc(bal & ((1u << lane) - 1u));
    if (isKey) kidx[meta[16 + wid] + rank] = tid;
    else       qidx[meta[32 + wid] + (lane - rank)] = tid;
    __syncthreads();
    const int nk = meta[48];
    const int nq = meta[49];

    // ---- phase 1: copy-through masked rows + stage compacted X (single read) ----
    const float4* xg4 = (const float4*)(x + (size_t)bp * S_ * D_);
    float4* og4 = (float4*)(out + (size_t)bp * S_ * D_);
    for (int i = tid; i < nk * 16; i += 512) {
        int j = i >> 4, c4 = i & 15;
        int s = kidx[j];
        float4 v = xg4[(size_t)s * 16 + c4];
        og4[(size_t)s * 16 + c4] = v;            // out = x for mask==1 rows
        int d0 = c4 << 2;
        // pair layout: Xs stores (x[d], x[d+32]) adjacent as a u64 per lane d
        int base = j * 64 + ((d0 & 31) << 1) + (d0 >> 5);
        Xs[base] = v.x; Xs[base + 2] = v.y; Xs[base + 4] = v.z; Xs[base + 6] = v.w;
    }
    __syncthreads();

    if (nq == 0) return;

    float* Ew0 = Ews + wid * 1024;
    float* Ew1 = Ew0 + 512;
    const float* gE = g_E + (size_t)b * S_ * S_;
    const float* xg = x + (size_t)bp * S_ * D_;
    float* og = out + (size_t)bp * S_ * D_;

    const int npairs = (nq + 1) >> 1;
    for (int pi = wid; pi < npairs; pi += 16) {
        int s0 = qidx[2 * pi];
        bool have1 = (2 * pi + 1) < nq;
        int s1 = have1 ? qidx[2 * pi + 1] : s0;

        // stage E rows (coalesced), premultiplied by mask
        const float4* er0 = (const float4*)(gE + (size_t)s0 * S_);
        const float4* er1 = (const float4*)(gE + (size_t)s1 * S_);
        const float4* m4 = (const float4*)m_row;
        float4* W0 = (float4*)Ew0;
        float4* W1 = (float4*)Ew1;
#pragma unroll
        for (int i = 0; i < 4; i++) {
            int ii = lane + (i << 5);
            float4 mm = m4[ii];
            float4 e0 = __ldg(er0 + ii);
            e0.x *= mm.x; e0.y *= mm.y; e0.z *= mm.z; e0.w *= mm.w;
            W0[ii] = e0;
            float4 e1 = __ldg(er1 + ii);
            e1.x *= mm.x; e1.y *= mm.y; e1.z *= mm.z; e1.w *= mm.w;
            W1[ii] = e1;
        }
        float Ess0 = __ldg(gE + (size_t)s0 * S_ + s0);
        float Ess1 = __ldg(gE + (size_t)s1 * S_ + s1);
        __syncwarp();

        // in-place compaction (kidx[j] >= j, so chunked read->sync->write is safe)
        // and denominator accumulation in the same pass
        float den0 = 0.0f, den1 = 0.0f;
        for (int base = 0; base < nk; base += 32) {
            int j = base + lane;
            float w0 = 0.0f, w1 = 0.0f;
            if (j < nk) { int tt = kidx[j]; w0 = Ew0[tt]; w1 = Ew1[tt]; }
            __syncwarp();
            if (j < nk) { Ew0[j] = w0; Ew1[j] = w1; }
            den0 += w0; den1 += w1;
        }
        __syncwarp();
#pragma unroll
        for (int off = 16; off; off >>= 1) {
            den0 += __shfl_xor_sync(0xffffffffu, den0, off);
            den1 += __shfl_xor_sync(0xffffffffu, den1, off);
        }
        den0 += Ess0; den1 += Ess1;       // diagonal always unmasked
        float rden0 = 1.0f / den0, rden1 = 1.0f / den1;

        // hot loop: packed f32x2 FMA, lane owns dims (lane, lane+32)
        u64 a0 = 0ull, a1 = 0ull;         // bit pattern of (0.0f, 0.0f)
        const u64* X2 = (const u64*)Xs;   // X2[j*32 + lane] = (x[lane], x[lane+32])
        int j = 0;
        for (; j + 8 <= nk; j += 8) {
#pragma unroll
            for (int u = 0; u < 8; u++) {
                u64 xv = X2[(size_t)(j + u) * 32 + lane];
                u64 w0d = pack2(Ew0[j + u]);
                u64 w1d = pack2(Ew1[j + u]);
                ffma2(a0, xv, w0d);
                ffma2(a1, xv, w1d);
            }
        }
        for (; j < nk; j++) {
            u64 xv = X2[(size_t)j * 32 + lane];
            ffma2(a0, xv, pack2(Ew0[j]));
            ffma2(a1, xv, pack2(Ew1[j]));
        }

        float a0lo, a0hi, a1lo, a1hi;
        unpack2(a0, a0lo, a0hi);
        unpack2(a1, a1lo, a1hi);

        // diagonal term + normalize + store (query rows have m==0: out = inter_x)
        float xd0 = xg[(size_t)s0 * D_ + lane];
        float xd0b = xg[(size_t)s0 * D_ + 32 + lane];
        og[(size_t)s0 * D_ + lane]      = (a0lo + Ess0 * xd0) * rden0;
        og[(size_t)s0 * D_ + 32 + lane] = (a0hi + Ess0 * xd0b) * rden0;
        if (have1) {
            float xd1 = xg[(size_t)s1 * D_ + lane];
            float xd1b = xg[(size_t)s1 * D_ + 32 + lane];
            og[(size_t)s1 * D_ + lane]      = (a1lo + Ess1 * xd1) * rden1;
            og[(size_t)s1 * D_ + 32 + lane] = (a1hi + Ess1 * xd1b) * rden1;
        }
    }
}

// ---------------- launch ----------------
extern "C" void kernel_launch(void* const* d_in, const int* in_sizes, int n_in,
                              void* d_out, int out_size) {
    const float* t = (const float*)d_in[0];
    const float* x = (const float*)d_in[1];
    const float* mask = (const float*)d_in[2];
    const float* alpha_w = (const float*)d_in[3];
    float* out = (float*)d_out;

    k_tpe<<<B_, S_>>>(t, alpha_w);
    k_escore<<<B_ * 32, 256>>>();

    const int smemC = (512 * 3 + 64 + 512 * 64 + 16 * 1024) * 4;   // 203,008 B
    cudaFuncSetAttribute(k_attn, cudaFuncAttributeMaxDynamicSharedMemorySize, smemC);
    k_attn<<<B_ * P_, 512, smemC>>>(x, mask, out);
}